// round 3
// baseline (speedup 1.0000x reference)
#include <cuda_runtime.h>
#include <cuda_bf16.h>
#include <stdint.h>

#define NG   4096
#define NPL  512
#define BB   64
#define SS   128
#define KC   64
#define NC   (NG / KC)
#define PAD  72
#define MAT_BYTES   (64 * PAD * 2)
#define STAGE_BYTES (4 * MAT_BYTES)
#define SMEM_BYTES  (2 * STAGE_BYTES)

__device__ __nv_bfloat16 g_Whh_hi[(size_t)NG * NG];
__device__ __nv_bfloat16 g_Whh_lo[(size_t)NG * NG];
__device__ __nv_bfloat16 g_Wdec_hi[(size_t)NPL * NG];
__device__ __nv_bfloat16 g_Wdec_lo[(size_t)NPL * NG];
__device__ __nv_bfloat16 g_h0_hi[BB * NG];
__device__ __nv_bfloat16 g_h0_lo[BB * NG];
__device__ __nv_bfloat16 g_hs_hi[(size_t)BB * SS * NG];
__device__ __nv_bfloat16 g_hs_lo[(size_t)BB * SS * NG];

__device__ __forceinline__ uint32_t smem_u32(const void* p) {
    return (uint32_t)__cvta_generic_to_shared(p);
}
__device__ __forceinline__ void cp16(uint32_t dst, const void* src) {
    asm volatile("cp.async.cg.shared.global [%0], [%1], 16;\n" :: "r"(dst), "l"(src));
}
__device__ __forceinline__ void cp_commit() {
    asm volatile("cp.async.commit_group;\n" ::: "memory");
}
__device__ __forceinline__ void cp_wait1() {
    asm volatile("cp.async.wait_group 1;\n" ::: "memory");
}
__device__ __forceinline__ void ldm_x4(uint32_t a, uint32_t& r0, uint32_t& r1,
                                       uint32_t& r2, uint32_t& r3) {
    asm volatile("ldmatrix.sync.aligned.m8n8.x4.shared.b16 {%0,%1,%2,%3}, [%4];\n"
                 : "=r"(r0), "=r"(r1), "=r"(r2), "=r"(r3) : "r"(a));
}
__device__ __forceinline__ void ldm_x2(uint32_t a, uint32_t& r0, uint32_t& r1) {
    asm volatile("ldmatrix.sync.aligned.m8n8.x2.shared.b16 {%0,%1}, [%2];\n"
                 : "=r"(r0), "=r"(r1) : "r"(a));
}
__device__ __forceinline__ void mma_bf16(float& d0, float& d1, float& d2, float& d3,
                                         uint32_t a0, uint32_t a1, uint32_t a2, uint32_t a3,
                                         uint32_t b0, uint32_t b1) {
    asm volatile(
        "mma.sync.aligned.m16n8k16.row.col.f32.bf16.bf16.f32 "
        "{%0,%1,%2,%3}, {%4,%5,%6,%7}, {%8,%9}, {%0,%1,%2,%3};\n"
        : "+f"(d0), "+f"(d1), "+f"(d2), "+f"(d3)
        : "r"(a0), "r"(a1), "r"(a2), "r"(a3), "r"(b0), "r"(b1));
}

// 512 threads: each moves one 16B chunk per matrix (Ahi, Alo, Bhi, Blo).
__device__ __forceinline__ void load_stage(
    const __nv_bfloat16* a_hi, const __nv_bfloat16* a_lo, size_t a_stride,
    const __nv_bfloat16* b_hi, const __nv_bfloat16* b_lo, size_t b_stride,
    uint32_t smbase, int stage, int kc)
{
    const int lrow = threadIdx.x >> 3;
    const int lcol = (threadIdx.x & 7) * 8;
    uint32_t dst = smbase + (uint32_t)stage * STAGE_BYTES
                 + (uint32_t)(lrow * PAD + lcol) * 2;
    size_t ao = (size_t)lrow * a_stride + kc + lcol;
    size_t bo = (size_t)lrow * b_stride + kc + lcol;
    cp16(dst,                 a_hi + ao);
    cp16(dst + 1 * MAT_BYTES, a_lo + ao);
    cp16(dst + 2 * MAT_BYTES, b_hi + bo);
    cp16(dst + 3 * MAT_BYTES, b_lo + bo);
}

// D(64x64) = A(64x4096) @ B(64x4096)^T via Ahi*Bhi + Alo*Bhi + Ahi*Blo, fp32 acc.
// 16 warps in 4x4 grid of 16x16 warp tiles.
__device__ __forceinline__ void gemm3_core(
    const __nv_bfloat16* a_hi, const __nv_bfloat16* a_lo, size_t a_stride,
    const __nv_bfloat16* b_hi, const __nv_bfloat16* b_lo, size_t b_stride,
    __nv_bfloat16* sm, float d[2][4])
{
    const int lane = threadIdx.x & 31;
    const int warp = threadIdx.x >> 5;
    const int wm = warp >> 2;
    const int wn = warp & 3;

    const int qa = lane >> 3, ra = lane & 7;
    const int a_row = wm * 16 + (qa & 1) * 8 + ra;
    const int a_col = (qa >> 1) * 8;
    const int qb = (lane >> 3) & 1, rb = lane & 7;
    const int b_row = wn * 16 + rb;
    const int b_col = qb * 8;

    const uint32_t smbase = smem_u32(sm);

    load_stage(a_hi, a_lo, a_stride, b_hi, b_lo, b_stride, smbase, 0, 0);
    cp_commit();

#pragma unroll 1
    for (int c = 0; c < NC; c++) {
        if (c + 1 < NC)
            load_stage(a_hi, a_lo, a_stride, b_hi, b_lo, b_stride,
                       smbase, (c + 1) & 1, (c + 1) * KC);
        cp_commit();
        cp_wait1();
        __syncthreads();

        const uint32_t sb = smbase + (uint32_t)(c & 1) * STAGE_BYTES;
#pragma unroll
        for (int ks = 0; ks < KC / 16; ks++) {
            const int k0 = ks * 16;
            uint32_t ah0, ah1, ah2, ah3, al0, al1, al2, al3;
            uint32_t aaddr = sb + (uint32_t)(a_row * PAD + a_col + k0) * 2;
            ldm_x4(aaddr,             ah0, ah1, ah2, ah3);
            ldm_x4(aaddr + MAT_BYTES, al0, al1, al2, al3);
#pragma unroll
            for (int j = 0; j < 2; j++) {
                uint32_t baddr = sb + 2 * MAT_BYTES
                               + (uint32_t)((b_row + j * 8) * PAD + b_col + k0) * 2;
                uint32_t bh0, bh1, bl0, bl1;
                ldm_x2(baddr,             bh0, bh1);
                ldm_x2(baddr + MAT_BYTES, bl0, bl1);
                mma_bf16(d[j][0], d[j][1], d[j][2], d[j][3], ah0, ah1, ah2, ah3, bh0, bh1);
                mma_bf16(d[j][0], d[j][1], d[j][2], d[j][3], al0, al1, al2, al3, bh0, bh1);
                mma_bf16(d[j][0], d[j][1], d[j][2], d[j][3], ah0, ah1, ah2, ah3, bl0, bl1);
            }
        }
        __syncthreads();
    }
}

__global__ void split_whh_kernel(const float* __restrict__ w) {
    const size_t n = (size_t)NG * NG;
    for (size_t i = (size_t)blockIdx.x * blockDim.x + threadIdx.x; i < n;
         i += (size_t)gridDim.x * blockDim.x) {
        float x = w[i];
        __nv_bfloat16 h = __float2bfloat16(x);
        g_Whh_hi[i] = h;
        g_Whh_lo[i] = __float2bfloat16(x - __bfloat162float(h));
    }
}
__global__ void split_wdec_kernel(const float* __restrict__ w) {
    const size_t n = (size_t)NPL * NG;
    for (size_t i = (size_t)blockIdx.x * blockDim.x + threadIdx.x; i < n;
         i += (size_t)gridDim.x * blockDim.x) {
        float x = w[i];
        __nv_bfloat16 h = __float2bfloat16(x);
        g_Wdec_hi[i] = h;
        g_Wdec_lo[i] = __float2bfloat16(x - __bfloat162float(h));
    }
}

// h0 = p0 @ W_init^T in exact fp32, split to hi/lo.
__global__ void h0_kernel(const float* __restrict__ p0, const float* __restrict__ Winit) {
    __shared__ float sP[64][33];
    __shared__ float sW[64][33];
    const int gbase = blockIdx.x * 64;
    const int tx = threadIdx.x & 15, ty = threadIdx.x >> 4;
    float acc[4][4] = {};
    for (int kc = 0; kc < 512; kc += 32) {
        for (int i = threadIdx.x; i < 64 * 32; i += 256) {
            int r = i >> 5, c = i & 31;
            sP[r][c] = p0[r * 512 + kc + c];
            sW[r][c] = Winit[(size_t)(gbase + r) * 512 + kc + c];
        }
        __syncthreads();
#pragma unroll
        for (int kk = 0; kk < 32; kk++) {
            float a[4], b[4];
#pragma unroll
            for (int i = 0; i < 4; i++) a[i] = sP[ty * 4 + i][kk];
#pragma unroll
            for (int j = 0; j < 4; j++) b[j] = sW[tx * 4 + j][kk];
#pragma unroll
            for (int i = 0; i < 4; i++)
#pragma unroll
                for (int j = 0; j < 4; j++) acc[i][j] = fmaf(a[i], b[j], acc[i][j]);
        }
        __syncthreads();
    }
#pragma unroll
    for (int i = 0; i < 4; i++) {
        int b = ty * 4 + i;
#pragma unroll
        for (int j = 0; j < 4; j++) {
            int g = gbase + tx * 4 + j;
            float h = acc[i][j];
            __nv_bfloat16 hh = __float2bfloat16(h);
            g_h0_hi[b * NG + g] = hh;
            g_h0_lo[b * NG + g] = __float2bfloat16(h - __bfloat162float(hh));
        }
    }
}

// One recurrence step: h_t = relu(W_ih v_t + W_hh h_{t-1}); writes hi/lo into history.
__global__ void __launch_bounds__(512, 1)
step_kernel(const float* __restrict__ v, const float* __restrict__ Wih, int t) {
    extern __shared__ __nv_bfloat16 smd[];
    __shared__ float s_v[BB][2];
    __shared__ float s_wih[64][2];

    const int gbase = blockIdx.x * 64;
    if (threadIdx.x < 128) {
        int b = threadIdx.x >> 1, i = threadIdx.x & 1;
        s_v[b][i] = v[(b * SS + t) * 2 + i];
        s_wih[b][i] = Wih[(gbase + b) * 2 + i];
    }

    const __nv_bfloat16 *ahi, *alo;
    size_t astr;
    if (t == 0) { ahi = g_h0_hi; alo = g_h0_lo; astr = NG; }
    else {
        ahi = g_hs_hi + (size_t)(t - 1) * NG;
        alo = g_hs_lo + (size_t)(t - 1) * NG;
        astr = (size_t)SS * NG;
    }

    float d[2][4] = {};
    gemm3_core(ahi, alo, astr,
               g_Whh_hi + (size_t)gbase * NG, g_Whh_lo + (size_t)gbase * NG, NG,
               smd, d);

    const int lane = threadIdx.x & 31;
    const int warp = threadIdx.x >> 5;
    const int wm = warp >> 2, wn = warp & 3;
    const int r0 = wm * 16 + (lane >> 2);
    const int c0 = wn * 16 + (lane & 3) * 2;

#pragma unroll
    for (int j = 0; j < 2; j++) {
#pragma unroll
        for (int hh = 0; hh < 2; hh++) {
            int b = r0 + hh * 8;
            int g = c0 + j * 8;
            float x0 = d[j][hh * 2 + 0] + s_v[b][0] * s_wih[g][0]     + s_v[b][1] * s_wih[g][1];
            float x1 = d[j][hh * 2 + 1] + s_v[b][0] * s_wih[g + 1][0] + s_v[b][1] * s_wih[g + 1][1];
            x0 = fmaxf(x0, 0.f);
            x1 = fmaxf(x1, 0.f);
            __nv_bfloat16 p0b = __float2bfloat16(x0), p1b = __float2bfloat16(x1);
            __nv_bfloat16 l0b = __float2bfloat16(x0 - __bfloat162float(p0b));
            __nv_bfloat16 l1b = __float2bfloat16(x1 - __bfloat162float(p1b));
            size_t o = ((size_t)b * SS + t) * NG + gbase + g;
            *(__nv_bfloat162*)&g_hs_hi[o] = __halves2bfloat162(p0b, p1b);
            *(__nv_bfloat162*)&g_hs_lo[o] = __halves2bfloat162(l0b, l1b);
        }
    }
}

// out = hs @ W_dec^T, fp32 out.
__global__ void __launch_bounds__(512, 1)
dec_kernel(float* __restrict__ out) {
    extern __shared__ __nv_bfloat16 smd[];
    const int mbase = blockIdx.x * 64;   // over B*S rows
    const int pbase = blockIdx.y * 64;   // over NPL cols

    float d[2][4] = {};
    gemm3_core(g_hs_hi + (size_t)mbase * NG, g_hs_lo + (size_t)mbase * NG, NG,
               g_Wdec_hi + (size_t)pbase * NG, g_Wdec_lo + (size_t)pbase * NG, NG,
               smd, d);

    const int lane = threadIdx.x & 31;
    const int warp = threadIdx.x >> 5;
    const int wm = warp >> 2, wn = warp & 3;
    const int rbase = mbase + wm * 16 + (lane >> 2);
    const int cbase = pbase + wn * 16 + (lane & 3) * 2;

#pragma unroll
    for (int j = 0; j < 2; j++) {
#pragma unroll
        for (int hh = 0; hh < 2; hh++) {
            int row = rbase + hh * 8;
            int col = cbase + j * 8;
            float2 v2 = make_float2(d[j][hh * 2 + 0], d[j][hh * 2 + 1]);
            *(float2*)&out[(size_t)row * NPL + col] = v2;
        }
    }
}

extern "C" void kernel_launch(void* const* d_in, const int* in_sizes, int n_in,
                              void* d_out, int out_size) {
    const float* v     = (const float*)d_in[0];
    const float* p0    = (const float*)d_in[1];
    const float* Winit = (const float*)d_in[2];
    const float* Wih   = (const float*)d_in[3];
    const float* Whh   = (const float*)d_in[4];
    const float* Wdec  = (const float*)d_in[5];
    float* out = (float*)d_out;

    cudaFuncSetAttribute(step_kernel, cudaFuncAttributeMaxDynamicSharedMemorySize, SMEM_BYTES);
    cudaFuncSetAttribute(dec_kernel,  cudaFuncAttributeMaxDynamicSharedMemorySize, SMEM_BYTES);

    split_whh_kernel<<<2048, 256>>>(Whh);
    split_wdec_kernel<<<512, 256>>>(Wdec);
    h0_kernel<<<64, 256>>>(p0, Winit);
    for (int t = 0; t < SS; t++)
        step_kernel<<<NC, 512, SMEM_BYTES>>>(v, Wih, t);
    dec_kernel<<<dim3(BB * SS / 64, NPL / 64), 512, SMEM_BYTES>>>(out);
}

// round 4
// speedup vs baseline: 1.7278x; 1.7278x over previous
#include <cuda_runtime.h>
#include <cuda_bf16.h>
#include <stdint.h>

#define NG   4096
#define NPL  512
#define BB   64
#define SS   128
#define KC   64
#define PAD  72
#define MAT_BYTES   (64 * PAD * 2)
#define STAGE_BYTES (4 * MAT_BYTES)
#define NSTAGE 3
#define SMEM3_BYTES (NSTAGE * STAGE_BYTES)
#define KSPLIT 4
#define KSEG  (NG / KSPLIT)          // 1024
#define NCSEG (KSEG / KC)            // 16 chunks per step CTA
#define NCDEC (NG / KC)              // 64 chunks for decoder

__device__ __nv_bfloat16 g_Whh_hi[(size_t)NG * NG];
__device__ __nv_bfloat16 g_Whh_lo[(size_t)NG * NG];
__device__ __nv_bfloat16 g_Wdec_hi[(size_t)NPL * NG];
__device__ __nv_bfloat16 g_Wdec_lo[(size_t)NPL * NG];
__device__ __nv_bfloat16 g_h0_hi[BB * NG];
__device__ __nv_bfloat16 g_h0_lo[BB * NG];
__device__ __nv_bfloat16 g_hs_hi[(size_t)BB * SS * NG];
__device__ __nv_bfloat16 g_hs_lo[(size_t)BB * SS * NG];
__device__ float g_part[(size_t)64 * KSPLIT * 64 * 64];   // [n][kq][b][g]
__device__ unsigned int g_cnt[64];                         // arrival counters (never reset)

__device__ __forceinline__ uint32_t smem_u32(const void* p) {
    return (uint32_t)__cvta_generic_to_shared(p);
}
__device__ __forceinline__ void cp16(uint32_t dst, const void* src) {
    asm volatile("cp.async.cg.shared.global [%0], [%1], 16;\n" :: "r"(dst), "l"(src));
}
__device__ __forceinline__ void cp_commit() {
    asm volatile("cp.async.commit_group;\n" ::: "memory");
}
__device__ __forceinline__ void cp_wait2() {
    asm volatile("cp.async.wait_group 2;\n" ::: "memory");
}
__device__ __forceinline__ void ldm_x4(uint32_t a, uint32_t& r0, uint32_t& r1,
                                       uint32_t& r2, uint32_t& r3) {
    asm volatile("ldmatrix.sync.aligned.m8n8.x4.shared.b16 {%0,%1,%2,%3}, [%4];\n"
                 : "=r"(r0), "=r"(r1), "=r"(r2), "=r"(r3) : "r"(a));
}
__device__ __forceinline__ void ldm_x2(uint32_t a, uint32_t& r0, uint32_t& r1) {
    asm volatile("ldmatrix.sync.aligned.m8n8.x2.shared.b16 {%0,%1}, [%2];\n"
                 : "=r"(r0), "=r"(r1) : "r"(a));
}
__device__ __forceinline__ void mma_bf16(float& d0, float& d1, float& d2, float& d3,
                                         uint32_t a0, uint32_t a1, uint32_t a2, uint32_t a3,
                                         uint32_t b0, uint32_t b1) {
    asm volatile(
        "mma.sync.aligned.m16n8k16.row.col.f32.bf16.bf16.f32 "
        "{%0,%1,%2,%3}, {%4,%5,%6,%7}, {%8,%9}, {%0,%1,%2,%3};\n"
        : "+f"(d0), "+f"(d1), "+f"(d2), "+f"(d3)
        : "r"(a0), "r"(a1), "r"(a2), "r"(a3), "r"(b0), "r"(b1));
}

// 512 threads: each moves one 16B chunk per matrix (Ahi, Alo, Bhi, Blo).
__device__ __forceinline__ void load_stage(
    const __nv_bfloat16* a_hi, const __nv_bfloat16* a_lo, size_t a_stride,
    const __nv_bfloat16* b_hi, const __nv_bfloat16* b_lo, size_t b_stride,
    uint32_t smbase, int stage, int kc)
{
    const int lrow = threadIdx.x >> 3;
    const int lcol = (threadIdx.x & 7) * 8;
    uint32_t dst = smbase + (uint32_t)stage * STAGE_BYTES
                 + (uint32_t)(lrow * PAD + lcol) * 2;
    size_t ao = (size_t)lrow * a_stride + kc + lcol;
    size_t bo = (size_t)lrow * b_stride + kc + lcol;
    cp16(dst,                 a_hi + ao);
    cp16(dst + 1 * MAT_BYTES, a_lo + ao);
    cp16(dst + 2 * MAT_BYTES, b_hi + bo);
    cp16(dst + 3 * MAT_BYTES, b_lo + bo);
}

// D(64x64) += A(64,K) @ B(64,K)^T via Ahi*Bhi + Alo*Bhi + Ahi*Blo, fp32 acc.
// 3-stage cp.async pipeline; 16 warps in 4x4 grid of 16x16 tiles.
__device__ __forceinline__ void gemm3_core(
    const __nv_bfloat16* a_hi, const __nv_bfloat16* a_lo, size_t a_stride,
    const __nv_bfloat16* b_hi, const __nv_bfloat16* b_lo, size_t b_stride,
    __nv_bfloat16* sm, float d[2][4], int nchunks)
{
    const int lane = threadIdx.x & 31;
    const int warp = threadIdx.x >> 5;
    const int wm = warp >> 2;
    const int wn = warp & 3;

    const int qa = lane >> 3, ra = lane & 7;
    const int a_row = wm * 16 + (qa & 1) * 8 + ra;
    const int a_col = (qa >> 1) * 8;
    const int qb = (lane >> 3) & 1, rb = lane & 7;
    const int b_row = wn * 16 + rb;
    const int b_col = qb * 8;

    const uint32_t smbase = smem_u32(sm);

    load_stage(a_hi, a_lo, a_stride, b_hi, b_lo, b_stride, smbase, 0, 0);
    cp_commit();
    load_stage(a_hi, a_lo, a_stride, b_hi, b_lo, b_stride, smbase, 1, KC);
    cp_commit();

#pragma unroll 1
    for (int c = 0; c < nchunks; c++) {
        if (c + 2 < nchunks)
            load_stage(a_hi, a_lo, a_stride, b_hi, b_lo, b_stride,
                       smbase, (c + 2) % NSTAGE, (c + 2) * KC);
        cp_commit();
        cp_wait2();
        __syncthreads();

        const uint32_t sb = smbase + (uint32_t)(c % NSTAGE) * STAGE_BYTES;
#pragma unroll
        for (int ks = 0; ks < KC / 16; ks++) {
            const int k0 = ks * 16;
            uint32_t ah0, ah1, ah2, ah3, al0, al1, al2, al3;
            uint32_t aaddr = sb + (uint32_t)(a_row * PAD + a_col + k0) * 2;
            ldm_x4(aaddr,             ah0, ah1, ah2, ah3);
            ldm_x4(aaddr + MAT_BYTES, al0, al1, al2, al3);
#pragma unroll
            for (int j = 0; j < 2; j++) {
                uint32_t baddr = sb + 2 * MAT_BYTES
                               + (uint32_t)((b_row + j * 8) * PAD + b_col + k0) * 2;
                uint32_t bh0, bh1, bl0, bl1;
                ldm_x2(baddr,             bh0, bh1);
                ldm_x2(baddr + MAT_BYTES, bl0, bl1);
                mma_bf16(d[j][0], d[j][1], d[j][2], d[j][3], ah0, ah1, ah2, ah3, bh0, bh1);
                mma_bf16(d[j][0], d[j][1], d[j][2], d[j][3], al0, al1, al2, al3, bh0, bh1);
                mma_bf16(d[j][0], d[j][1], d[j][2], d[j][3], ah0, ah1, ah2, ah3, bl0, bl1);
            }
        }
        __syncthreads();
    }
}

__global__ void split_whh_kernel(const float* __restrict__ w) {
    const size_t n = (size_t)NG * NG;
    for (size_t i = (size_t)blockIdx.x * blockDim.x + threadIdx.x; i < n;
         i += (size_t)gridDim.x * blockDim.x) {
        float x = w[i];
        __nv_bfloat16 h = __float2bfloat16(x);
        g_Whh_hi[i] = h;
        g_Whh_lo[i] = __float2bfloat16(x - __bfloat162float(h));
    }
}
__global__ void split_wdec_kernel(const float* __restrict__ w) {
    const size_t n = (size_t)NPL * NG;
    for (size_t i = (size_t)blockIdx.x * blockDim.x + threadIdx.x; i < n;
         i += (size_t)gridDim.x * blockDim.x) {
        float x = w[i];
        __nv_bfloat16 h = __float2bfloat16(x);
        g_Wdec_hi[i] = h;
        g_Wdec_lo[i] = __float2bfloat16(x - __bfloat162float(h));
    }
}

// h0 = p0 @ W_init^T in exact fp32, split to hi/lo.
__global__ void h0_kernel(const float* __restrict__ p0, const float* __restrict__ Winit) {
    __shared__ float sP[64][33];
    __shared__ float sW[64][33];
    const int gbase = blockIdx.x * 64;
    const int tx = threadIdx.x & 15, ty = threadIdx.x >> 4;
    float acc[4][4] = {};
    for (int kc = 0; kc < 512; kc += 32) {
        for (int i = threadIdx.x; i < 64 * 32; i += 256) {
            int r = i >> 5, c = i & 31;
            sP[r][c] = p0[r * 512 + kc + c];
            sW[r][c] = Winit[(size_t)(gbase + r) * 512 + kc + c];
        }
        __syncthreads();
#pragma unroll
        for (int kk = 0; kk < 32; kk++) {
            float a[4], b[4];
#pragma unroll
            for (int i = 0; i < 4; i++) a[i] = sP[ty * 4 + i][kk];
#pragma unroll
            for (int j = 0; j < 4; j++) b[j] = sW[tx * 4 + j][kk];
#pragma unroll
            for (int i = 0; i < 4; i++)
#pragma unroll
                for (int j = 0; j < 4; j++) acc[i][j] = fmaf(a[i], b[j], acc[i][j]);
        }
        __syncthreads();
    }
#pragma unroll
    for (int i = 0; i < 4; i++) {
        int b = ty * 4 + i;
#pragma unroll
        for (int j = 0; j < 4; j++) {
            int g = gbase + tx * 4 + j;
            float h = acc[i][j];
            __nv_bfloat16 hh = __float2bfloat16(h);
            g_h0_hi[b * NG + g] = hh;
            g_h0_lo[b * NG + g] = __float2bfloat16(h - __bfloat162float(hh));
        }
    }
}

// One recurrence step, K-split x4. blockIdx.x = n-slab, blockIdx.y = K-quarter.
// Last-arriving CTA per n-slab fuses: sum partials + Wih*v + relu + hi/lo split.
__global__ void __launch_bounds__(512, 2)
step_kernel(const float* __restrict__ v, const float* __restrict__ Wih, int t) {
    extern __shared__ __nv_bfloat16 smd[];
    __shared__ int s_last;

    const int n = blockIdx.x;
    const int kq = blockIdx.y;
    const int gbase = n * 64;
    const int kbase = kq * KSEG;

    const __nv_bfloat16 *ahi, *alo;
    size_t astr;
    if (t == 0) { ahi = g_h0_hi; alo = g_h0_lo; astr = NG; }
    else {
        ahi = g_hs_hi + (size_t)(t - 1) * NG;
        alo = g_hs_lo + (size_t)(t - 1) * NG;
        astr = (size_t)SS * NG;
    }

    float d[2][4] = {};
    gemm3_core(ahi + kbase, alo + kbase, astr,
               g_Whh_hi + (size_t)gbase * NG + kbase,
               g_Whh_lo + (size_t)gbase * NG + kbase, NG,
               smd, d, NCSEG);

    // write fp32 partial tile [b][g] (64x64)
    float* part = g_part + ((size_t)n * KSPLIT + kq) * 64 * 64;
    {
        const int lane = threadIdx.x & 31;
        const int warp = threadIdx.x >> 5;
        const int wm = warp >> 2, wn = warp & 3;
        const int r0 = wm * 16 + (lane >> 2);
        const int c0 = wn * 16 + (lane & 3) * 2;
#pragma unroll
        for (int j = 0; j < 2; j++)
#pragma unroll
            for (int hh = 0; hh < 2; hh++)
                *(float2*)&part[(r0 + hh * 8) * 64 + c0 + j * 8] =
                    make_float2(d[j][hh * 2 + 0], d[j][hh * 2 + 1]);
    }
    __syncthreads();
    if (threadIdx.x == 0) {
        __threadfence();
        unsigned int old = atomicAdd(&g_cnt[n], 1u);
        s_last = ((old & 3u) == 3u) ? 1 : 0;
    }
    __syncthreads();
    if (!s_last) return;

    // fused epilogue by last arriver
    const float* pb = g_part + (size_t)n * KSPLIT * 64 * 64;
    for (int i = threadIdx.x; i < 64 * 64; i += 512) {
        int b = i >> 6, g = i & 63;
        float x = pb[i] + pb[4096 + i] + pb[8192 + i] + pb[12288 + i];
        float v0 = v[(b * SS + t) * 2 + 0];
        float v1 = v[(b * SS + t) * 2 + 1];
        x += v0 * Wih[(gbase + g) * 2 + 0] + v1 * Wih[(gbase + g) * 2 + 1];
        x = fmaxf(x, 0.f);
        __nv_bfloat16 xh = __float2bfloat16(x);
        size_t o = ((size_t)b * SS + t) * NG + gbase + g;
        g_hs_hi[o] = xh;
        g_hs_lo[o] = __float2bfloat16(x - __bfloat162float(xh));
    }
}

// out = hs @ W_dec^T, fp32 out.
__global__ void __launch_bounds__(512, 2)
dec_kernel(float* __restrict__ out) {
    extern __shared__ __nv_bfloat16 smd[];
    const int mbase = blockIdx.x * 64;   // over B*S rows
    const int pbase = blockIdx.y * 64;   // over NPL cols

    float d[2][4] = {};
    gemm3_core(g_hs_hi + (size_t)mbase * NG, g_hs_lo + (size_t)mbase * NG, NG,
               g_Wdec_hi + (size_t)pbase * NG, g_Wdec_lo + (size_t)pbase * NG, NG,
               smd, d, NCDEC);

    const int lane = threadIdx.x & 31;
    const int warp = threadIdx.x >> 5;
    const int wm = warp >> 2, wn = warp & 3;
    const int rbase = mbase + wm * 16 + (lane >> 2);
    const int cbase = pbase + wn * 16 + (lane & 3) * 2;

#pragma unroll
    for (int j = 0; j < 2; j++)
#pragma unroll
        for (int hh = 0; hh < 2; hh++) {
            int row = rbase + hh * 8;
            int col = cbase + j * 8;
            *(float2*)&out[(size_t)row * NPL + col] =
                make_float2(d[j][hh * 2 + 0], d[j][hh * 2 + 1]);
        }
}

extern "C" void kernel_launch(void* const* d_in, const int* in_sizes, int n_in,
                              void* d_out, int out_size) {
    const float* v     = (const float*)d_in[0];
    const float* p0    = (const float*)d_in[1];
    const float* Winit = (const float*)d_in[2];
    const float* Wih   = (const float*)d_in[3];
    const float* Whh   = (const float*)d_in[4];
    const float* Wdec  = (const float*)d_in[5];
    float* out = (float*)d_out;

    cudaFuncSetAttribute(step_kernel, cudaFuncAttributeMaxDynamicSharedMemorySize, SMEM3_BYTES);
    cudaFuncSetAttribute(dec_kernel,  cudaFuncAttributeMaxDynamicSharedMemorySize, SMEM3_BYTES);

    split_whh_kernel<<<2048, 256>>>(Whh);
    split_wdec_kernel<<<512, 256>>>(Wdec);
    h0_kernel<<<64, 256>>>(p0, Winit);
    for (int t = 0; t < SS; t++)
        step_kernel<<<dim3(64, KSPLIT), 512, SMEM3_BYTES>>>(v, Wih, t);
    dec_kernel<<<dim3(BB * SS / 64, NPL / 64), 512, SMEM3_BYTES>>>(out);
}